// round 8
// baseline (speedup 1.0000x reference)
#include <cuda_runtime.h>

#define IMG      512
#define CROPPED  504
#define BATCH    16
#define TILE     32          // 32x32 output tile
#define VW       42          // TILE + 10 columns in vv
#define VH       32
#define VSTRIDE  43          // odd stride -> conflict-free bank groups
#define NCHUNKS  6
#define CHUNK_A  6           // 6*6 = 36 >= 32 rows (tail predicated)
#define ROWS_LD  16          // CHUNK_A + 10 input rows per thread
#define NTX      16          // ceil(504/32)
#define NTY      16
#define TOTAL_CTAS (NTX * NTY * BATCH)   // 4096

__device__ double   g_acc;    // zero at module load; last CTA resets each call
__device__ unsigned g_count;

__global__ __launch_bounds__(256, 4) void ssim_main_kernel(
    const float* __restrict__ img1, const float* __restrict__ img2,
    float* __restrict__ out)
{
    // packed vertical 11-row running sums: {S1, S2, S11+S22, S12}
    __shared__ float4 vv[VH][VSTRIDE];

    const int b   = blockIdx.z;
    const int tj0 = blockIdx.x * TILE;
    const int ti0 = blockIdx.y * TILE;
    const int tid = threadIdx.x;

    const size_t base = (size_t)b * 3u * IMG * IMG;   // channel 0 of batch b

    // ===== Phase A: vertical sums; whole footprint in registers ============
    // thread (c, chunk): column c, 6 output rows. Loads its 16 input rows x 2
    // images as 32 INDEPENDENT LDGs (MLP ~32, one exposed latency), then all
    // arithmetic is register-resident. No input smem, no serial LDG chain.
    if (tid < VW * NCHUNKS) {
        const int c     = tid % VW;
        const int chunk = tid / VW;
        const int r0    = chunk * CHUNK_A;
        const int gj    = tj0 - 5 + c;
        const bool colok = (unsigned)gj < (unsigned)CROPPED;
        const float* p1 = img1 + base + (gj + 4);
        const float* p2 = img2 + base + (gj + 4);

        float a_w[ROWS_LD], b_w[ROWS_LD];
        #pragma unroll
        for (int k = 0; k < ROWS_LD; k++) {
            const int gi = ti0 + r0 - 5 + k;
            const bool ok = colok && ((unsigned)gi < (unsigned)CROPPED);
            const size_t roff = (size_t)(gi + 4) * IMG;
            a_w[k] = ok ? __ldg(p1 + roff) : 0.f;
            b_w[k] = ok ? __ldg(p2 + roff) : 0.f;
        }

        float s1 = 0.f, s2 = 0.f, sA = 0.f, s12 = 0.f;
        #pragma unroll
        for (int k = 0; k < 11; k++) {
            const float a  = a_w[k];
            const float bb = b_w[k];
            s1  += a;
            s2  += bb;
            sA   = fmaf(a, a, fmaf(bb, bb, sA));
            s12  = fmaf(a, bb, s12);
        }
        vv[r0][c] = make_float4(s1, s2, sA, s12);

        #pragma unroll
        for (int t = 1; t < CHUNK_A; t++) {
            const int r = r0 + t;
            const float an = a_w[t + 10];
            const float bn = b_w[t + 10];
            const float ao = a_w[t - 1];
            const float bo = b_w[t - 1];
            s1  += an - ao;
            s2  += bn - bo;
            sA  += fmaf(an, an, bn * bn) - fmaf(ao, ao, bo * bo);
            s12 += an * bn - ao * bo;
            if (r < VH) vv[r][c] = make_float4(s1, s2, sA, s12);
        }
    }
    __syncthreads();

    // ===== Phase B: horizontal sliding + SSIM ===============================
    // i = tid&31 (row), seg = tid>>5 (0..7), 4 cols/thread; LDS.128 octets
    // have consecutive i -> bank group (12i+4j) mod 32 distinct -> no conflict.
    const float C1   = 6.5025f;                // (0.01*255)^2
    const float C2   = 58.5225f;               // (0.03*255)^2
    const float inv  = 1.0f / 121.0f;
    const float SCL  = 1.52587890625e-5f;      // 2^-16 pre-scale

    float local = 0.0f;
    {
        const int i  = tid & 31;
        const int j0 = (tid >> 5) * 4;

        if (ti0 + i < CROPPED) {
            float S1 = 0.f, S2 = 0.f, SA = 0.f, S12 = 0.f;
            #pragma unroll
            for (int k = 0; k < 11; k++) {
                const float4 t = vv[i][j0 + k];
                S1  += t.x;
                S2  += t.y;
                SA  += t.z;
                S12 += t.w;
            }

            float n[4], d[4];
            #pragma unroll
            for (int t = 0; t < 4; t++) {
                const int j = j0 + t;
                if (tj0 + j < CROPPED) {
                    const float mu1  = S1 * inv;
                    const float mu2  = S2 * inv;
                    const float m1s  = mu1 * mu1;
                    const float m2s  = mu2 * mu2;
                    const float m12  = mu1 * mu2;
                    const float sgA  = SA  * inv - m1s - m2s;  // sig1^2+sig2^2
                    const float sg12 = S12 * inv - m12;
                    const float num  = (2.0f * m12 + C1) * (2.0f * sg12 + C2);
                    const float den  = (m1s + m2s + C1) * (sgA + C2);
                    n[t] = num * SCL;
                    d[t] = den * SCL;
                } else {
                    n[t] = 0.0f;
                    d[t] = 1.0f;
                }
                if (t < 3) {   // slide: add col j+11, drop col j
                    const float4 va = vv[i][j + 11];
                    const float4 vs = vv[i][j];
                    S1  += va.x - vs.x;
                    S2  += va.y - vs.y;
                    SA  += va.z - vs.z;
                    S12 += va.w - vs.w;
                }
            }

            // 4-way ratio combine: one MUFU rcp per 4 pixels
            const float n12 = n[0] * d[1] + n[1] * d[0];
            const float d12 = d[0] * d[1];
            const float n34 = n[2] * d[3] + n[3] * d[2];
            const float d34 = d[2] * d[3];
            const float N   = n12 * d34 + n34 * d12;
            const float D   = d12 * d34;
            local += __fdividef(N, D);
        }
    }

    // ===== Block reduction -> one double atomic =============================
    #pragma unroll
    for (int o = 16; o > 0; o >>= 1)
        local += __shfl_down_sync(0xffffffffu, local, o);

    __shared__ float warpsum[8];
    if ((tid & 31) == 0) warpsum[tid >> 5] = local;
    __syncthreads();

    if (tid == 0) {
        float v = warpsum[0];
        #pragma unroll
        for (int w = 1; w < 8; w++) v += warpsum[w];
        atomicAdd(&g_acc, (double)v);

        // ---- last-CTA finalize ----
        __threadfence();
        const unsigned ticket = atomicAdd(&g_count, 1u);
        if (ticket == TOTAL_CTAS - 1) {
            const double acc = g_acc;
            out[0] = (float)(acc / ((double)BATCH * CROPPED * CROPPED));
            g_acc   = 0.0;   // reset for next graph replay
            g_count = 0u;
            __threadfence();
        }
    }
}

extern "C" void kernel_launch(void* const* d_in, const int* in_sizes, int n_in,
                              void* d_out, int out_size)
{
    const float* img1 = (const float*)d_in[0];
    const float* img2 = (const float*)d_in[1];
    float* out = (float*)d_out;

    dim3 grid(NTX, NTY, BATCH);
    ssim_main_kernel<<<grid, 256>>>(img1, img2, out);
}

// round 13
// speedup vs baseline: 1.2309x; 1.2309x over previous
#include <cuda_runtime.h>

#define IMG      512
#define CROPPED  504
#define BATCH    16
#define TILE_W   32
#define TILE_H   54
#define HROWS    64          // TILE_H + 10 input rows
#define HPAD     66          // + 2 zeroed pad rows for chunk-7 slides
#define HS       33          // col stride (float2 elems) -> conflict-free banks
#define NTX      16          // ceil(504/32)
#define NTY      10          // ceil(504/54)
#define TOTAL_CTAS (NTX * NTY * BATCH)   // 2560

__device__ double   g_acc;    // zero at module load; last CTA resets each call
__device__ unsigned g_count;

__global__ __launch_bounds__(256, 4) void ssim_main_kernel(
    const float* __restrict__ img1, const float* __restrict__ img2,
    float* __restrict__ out)
{
    // horizontal 11-sums per input row: {S1,S2} and {SA=S11+S22, S12}
    __shared__ float2 hlo[HPAD][HS];
    __shared__ float2 hhi[HPAD][HS];

    const int b   = blockIdx.z;
    const int tj0 = blockIdx.x * TILE_W;
    const int ti0 = blockIdx.y * TILE_H;
    const int tid = threadIdx.x;

    const size_t base = (size_t)b * 3u * IMG * IMG;   // channel 0 of batch b

    // ===== zero the 2 pad rows (64,65), cols 0..31, both arrays ===========
    if (tid < 128) {
        const int r = HROWS + (tid & 1);
        const int c = (tid >> 1) & 31;
        if (tid < 64) hlo[r][c] = make_float2(0.f, 0.f);
        else          hhi[r][c] = make_float2(0.f, 0.f);
    }

    // ===== Phase A: horizontal 11-sums, vectorized gmem loads =============
    // thread (row, seg): input row, 8 output cols. 24-float window per image
    // = 6 aligned LDG.128. All sliding arithmetic register-resident.
    {
        const int row = tid >> 2;          // 0..63
        const int seg = tid & 3;
        const int j0  = seg << 3;          // 0,8,16,24
        const int gi  = ti0 - 5 + row;     // cropped-row of this h row
        const int gjb = tj0 + j0 - 8;      // cropped-col of a[0]
        const bool rowok = (unsigned)gi < (unsigned)CROPPED;

        float a[24], bb[24];
        if (rowok) {
            const float4* p1 = (const float4*)(img1 + base + (size_t)(gi + 4) * IMG + (gjb + 4));
            const float4* p2 = (const float4*)(img2 + base + (size_t)(gi + 4) * IMG + (gjb + 4));
            #pragma unroll
            for (int q = 0; q < 6; q++) {
                const float4 va = __ldg(p1 + q);
                const float4 vb = __ldg(p2 + q);
                a [4*q+0] = va.x; a [4*q+1] = va.y; a [4*q+2] = va.z; a [4*q+3] = va.w;
                bb[4*q+0] = vb.x; bb[4*q+1] = vb.y; bb[4*q+2] = vb.z; bb[4*q+3] = vb.w;
            }
        } else {
            #pragma unroll
            for (int m = 0; m < 24; m++) { a[m] = 0.f; bb[m] = 0.f; }
        }
        // column masking only needed in the two x-edge CTA columns (uniform)
        if (blockIdx.x == 0 || blockIdx.x == NTX - 1) {
            #pragma unroll
            for (int m = 0; m < 24; m++)
                if ((unsigned)(gjb + m) >= (unsigned)CROPPED) { a[m] = 0.f; bb[m] = 0.f; }
        }

        // output col j0+t has window m = t+3 .. t+13
        float s1 = 0.f, s2 = 0.f, sA = 0.f, s12 = 0.f;
        #pragma unroll
        for (int k = 3; k < 14; k++) {
            s1  += a[k];
            s2  += bb[k];
            sA   = fmaf(a[k], a[k], fmaf(bb[k], bb[k], sA));
            s12  = fmaf(a[k], bb[k], s12);
        }
        hlo[row][j0] = make_float2(s1, s2);
        hhi[row][j0] = make_float2(sA, s12);

        #pragma unroll
        for (int t = 1; t < 8; t++) {
            const float an = a[t + 13], bn = bb[t + 13];
            const float ao = a[t + 2],  bo = bb[t + 2];
            s1  += an - ao;
            s2  += bn - bo;
            sA  += fmaf(an, an, bn * bn) - fmaf(ao, ao, bo * bo);
            s12 += an * bn - ao * bo;
            hlo[row][j0 + t] = make_float2(s1, s2);
            hhi[row][j0 + t] = make_float2(sA, s12);
        }
    }
    __syncthreads();

    // ===== Phase B: vertical 11-sliding + SSIM ============================
    // j = tid&31 (col), chunk = tid>>5 (0..7), 7 rows/thread (56 >= 54).
    // Rows r >= TILE_H belong to the NEXT tile: must NOT be accumulated here
    // (R9 bug: double count + pad-polluted windows).
    const float C1  = 6.5025f;                 // (0.01*255)^2
    const float C2  = 58.5225f;                // (0.03*255)^2
    const float inv = 1.0f / 121.0f;
    const float SCL = 1.52587890625e-5f;       // 2^-16 pre-scale

    float local = 0.0f;
    {
        const int j  = tid & 31;
        const int r0 = (tid >> 5) * 7;
        const bool colok = (tj0 + j) < CROPPED;

        float S1 = 0.f, S2 = 0.f, SA = 0.f, S12 = 0.f;
        #pragma unroll
        for (int k = 0; k < 11; k++) {
            const float2 lo = hlo[r0 + k][j];
            const float2 hi = hhi[r0 + k][j];
            S1 += lo.x; S2 += lo.y; SA += hi.x; S12 += hi.y;
        }

        float n[7], d[7];
        #pragma unroll
        for (int t = 0; t < 7; t++) {
            const int r = r0 + t;
            if (colok && r < TILE_H && (ti0 + r) < CROPPED) {
                const float mu1  = S1 * inv;
                const float mu2  = S2 * inv;
                const float m1s  = mu1 * mu1;
                const float m2s  = mu2 * mu2;
                const float m12  = mu1 * mu2;
                const float sgA  = SA  * inv - m1s - m2s;   // sig1^2 + sig2^2
                const float sg12 = S12 * inv - m12;
                const float num  = (2.0f * m12 + C1) * (2.0f * sg12 + C2);
                const float den  = (m1s + m2s + C1) * (sgA + C2);
                n[t] = num * SCL;
                d[t] = den * SCL;
            } else {
                n[t] = 0.0f;
                d[t] = 1.0f;
            }
            if (t < 6) {   // slide: add h row r+11, drop h row r
                const float2 loa = hlo[r + 11][j];
                const float2 los = hlo[r][j];
                const float2 hia = hhi[r + 11][j];
                const float2 his = hhi[r][j];
                S1  += loa.x - los.x;
                S2  += loa.y - los.y;
                SA  += hia.x - his.x;
                S12 += hia.y - his.y;
            }
        }

        // 7 ratios with 2 MUFU rcp: groups of 4 and 3
        const float n12 = n[0] * d[1] + n[1] * d[0];
        const float d12 = d[0] * d[1];
        const float n34 = n[2] * d[3] + n[3] * d[2];
        const float d34 = d[2] * d[3];
        const float N4  = n12 * d34 + n34 * d12;
        const float D4  = d12 * d34;
        const float n56 = n[4] * d[5] + n[5] * d[4];
        const float d56 = d[4] * d[5];
        const float N3  = n56 * d[6] + n[6] * d56;
        const float D3  = d56 * d[6];
        local = __fdividef(N4, D4) + __fdividef(N3, D3);
    }

    // ===== Block reduction -> one double atomic ===========================
    #pragma unroll
    for (int o = 16; o > 0; o >>= 1)
        local += __shfl_down_sync(0xffffffffu, local, o);

    __shared__ float warpsum[8];
    if ((tid & 31) == 0) warpsum[tid >> 5] = local;
    __syncthreads();

    if (tid == 0) {
        float v = warpsum[0];
        #pragma unroll
        for (int w = 1; w < 8; w++) v += warpsum[w];
        atomicAdd(&g_acc, (double)v);

        // ---- last-CTA finalize ----
        __threadfence();
        const unsigned ticket = atomicAdd(&g_count, 1u);
        if (ticket == TOTAL_CTAS - 1) {
            const double acc = g_acc;
            out[0] = (float)(acc / ((double)BATCH * CROPPED * CROPPED));
            g_acc   = 0.0;   // reset for next graph replay
            g_count = 0u;
            __threadfence();
        }
    }
}

extern "C" void kernel_launch(void* const* d_in, const int* in_sizes, int n_in,
                              void* d_out, int out_size)
{
    const float* img1 = (const float*)d_in[0];
    const float* img2 = (const float*)d_in[1];
    float* out = (float*)d_out;

    dim3 grid(NTX, NTY, BATCH);
    ssim_main_kernel<<<grid, 256>>>(img1, img2, out);
}